// round 3
// baseline (speedup 1.0000x reference)
#include <cuda_runtime.h>

#define DD     262144     // 512*512
#define NB     128        // batch
#define NENV   4
#define KSEL   26214      // floor(0.1 * 512 * 512)
#define NBIN   65536

// Scratch (allocation-free: __device__ globals)
__device__ float    g_M[NENV][DD];        // per-env logits
__device__ float    g_S[NENV][DD];        // per-env sigmoid(logits)
__device__ unsigned g_hist[NENV][NBIN];   // radix pass 1 (hi 16 bits)
__device__ unsigned g_hist2[NENV][NBIN];  // radix pass 2 (lo 16 bits)
__device__ unsigned g_binhi[NENV];
__device__ unsigned g_rank[NENV];
__device__ unsigned g_kth[NENV];          // exact key of k-th largest per env
__device__ int      g_rows[NENV][NB];     // batch rows belonging to each env
__device__ int      g_nrows[NENV];

// Monotone mapping: float total order -> unsigned total order
__device__ __forceinline__ unsigned fkey(float f) {
    unsigned u = __float_as_uint(f);
    return (u & 0x80000000u) ? ~u : (u | 0x80000000u);
}
__device__ __forceinline__ float sigm(float x) {
    return __fdividef(1.0f, 1.0f + __expf(-x));   // MUFU EX2 + MUFU RCP
}

__global__ void k_zero() {
    int stride = gridDim.x * blockDim.x;
    unsigned* h1 = &g_hist[0][0];
    for (int j = blockIdx.x * blockDim.x + threadIdx.x; j < NENV * NBIN; j += stride)
        h1[j] = 0u;
}

// Build per-env logits + sigmoid + hi-16 histogram. MLP=4 (4 strided float4/thread).
__global__ void k_build(const float* __restrict__ base, const float* __restrict__ deltas) {
    int e = blockIdx.y;
    int blockBase = blockIdx.x * 4096;             // 256 thr * 4 f4 * 4 floats
    #pragma unroll
    for (int j = 0; j < 4; j++) {
        int i = blockBase + (j * 256 + threadIdx.x) * 4;
        float4 b4 = *(const float4*)(base + i);
        float4 d4 = *(const float4*)(deltas + (size_t)e * DD + i);
        float4 m;
        m.x = b4.x + d4.x; m.y = b4.y + d4.y;
        m.z = b4.z + d4.z; m.w = b4.w + d4.w;
        *(float4*)(&g_M[e][i]) = m;
        float4 s;
        s.x = sigm(m.x); s.y = sigm(m.y); s.z = sigm(m.z); s.w = sigm(m.w);
        *(float4*)(&g_S[e][i]) = s;
        atomicAdd(&g_hist[e][fkey(m.x) >> 16], 1u);
        atomicAdd(&g_hist[e][fkey(m.y) >> 16], 1u);
        atomicAdd(&g_hist[e][fkey(m.z) >> 16], 1u);
        atomicAdd(&g_hist[e][fkey(m.w) >> 16], 1u);
    }
}

// Rank-select scan over a 65536-bin histogram (descending). Parallel suffix-scan.
// phase 0: g_hist -> (binhi, remaining rank); also zeroes g_hist2.
// phase 1: g_hist2 -> exact kth key; also compacts per-env batch row lists.
__global__ void k_scan(int phase, const int* __restrict__ env_idx) {
    int e = blockIdx.x;
    int t = threadIdx.x;
    const unsigned* h = (phase == 0) ? &g_hist[e][0] : &g_hist2[e][0];
    __shared__ unsigned ss[1024];
    __shared__ int cnt;

    unsigned s = 0;
    #pragma unroll 4
    for (int j = 0; j < 64; j++) {
        s += h[t * 64 + j];
        if (phase == 0) g_hist2[e][t * 64 + j] = 0u;   // prep pass 2
    }
    ss[t] = s;
    __syncthreads();
    // inclusive suffix sum: ss[t] = sum_{j>=t} chunk[j]
    for (int off = 1; off < 1024; off <<= 1) {
        unsigned v = (t + off < 1024) ? ss[t + off] : 0u;
        __syncthreads();
        ss[t] += v;
        __syncthreads();
    }
    unsigned target = (phase == 0) ? (unsigned)KSEL : g_rank[e];
    unsigned above = (t < 1023) ? ss[t + 1] : 0u;
    if (ss[t] >= target && above < target) {
        // kth key lies in chunk t; walk its 64 bins descending
        unsigned cum = above;
        unsigned bin = (unsigned)(t * 64);
        for (int j = 63; j >= 0; j--) {
            unsigned v = h[t * 64 + j];
            if (cum + v >= target) { bin = (unsigned)(t * 64 + j); break; }
            cum += v;
        }
        if (phase == 0) {
            g_binhi[e] = bin;
            g_rank[e]  = target - cum;
        } else {
            g_kth[e] = (g_binhi[e] << 16) | bin;
        }
    }
    if (phase == 1) {
        if (t == 0) cnt = 0;
        __syncthreads();
        if (t < NB) {
            if (env_idx[t] == e) {
                int p = atomicAdd(&cnt, 1);
                g_rows[e][p] = t;
            }
        }
        __syncthreads();
        if (t == 0) g_nrows[e] = cnt;
    }
}

// Lo-16 histogram restricted to the selected hi-bin. MLP=4.
__global__ void k_hist2() {
    int e = blockIdx.y;
    unsigned hi = g_binhi[e];
    int blockBase = blockIdx.x * 4096;
    #pragma unroll
    for (int j = 0; j < 4; j++) {
        int i = blockBase + (j * 256 + threadIdx.x) * 4;
        float4 m = *(const float4*)(&g_M[e][i]);
        unsigned k0 = fkey(m.x), k1 = fkey(m.y), k2 = fkey(m.z), k3 = fkey(m.w);
        if ((k0 >> 16) == hi) atomicAdd(&g_hist2[e][k0 & 0xFFFFu], 1u);
        if ((k1 >> 16) == hi) atomicAdd(&g_hist2[e][k1 & 0xFFFFu], 1u);
        if ((k2 >> 16) == hi) atomicAdd(&g_hist2[e][k2 & 0xFFFFu], 1u);
        if ((k3 >> 16) == hi) atomicAdd(&g_hist2[e][k3 & 0xFFFFu], 1u);
    }
}

// Broadcast writer: load each env chunk ONCE, store to all batch rows of that env.
// Pure store-bound: 32 MB reads (L2-hot) vs 402 MB streaming stores.
__global__ void k_bcast(float* __restrict__ outA,
                        float* __restrict__ outL,
                        float* __restrict__ outS) {
    int e = blockIdx.y;
    __shared__ int rows_s[NB];
    __shared__ int nr_s;
    if (threadIdx.x == 0) nr_s = g_nrows[e];
    if (threadIdx.x < NB) rows_s[threadIdx.x] = g_rows[e][threadIdx.x];

    int i = (blockIdx.x * 256 + threadIdx.x) * 4;
    float4 m = *(const float4*)(&g_M[e][i]);
    float4 s = *(const float4*)(&g_S[e][i]);
    unsigned kth = g_kth[e];
    float4 a;
    a.x = (fkey(m.x) >= kth) ? s.x : 0.0f;
    a.y = (fkey(m.y) >= kth) ? s.y : 0.0f;
    a.z = (fkey(m.z) >= kth) ? s.z : 0.0f;
    a.w = (fkey(m.w) >= kth) ? s.w : 0.0f;
    __syncthreads();

    int nr = nr_s;
    for (int r = 0; r < nr; r++) {
        size_t off = (size_t)rows_s[r] * DD + i;
        __stcs((float4*)(outA + off), a);
        __stcs((float4*)(outL + off), m);
        __stcs((float4*)(outS + off), s);
    }
}

extern "C" void kernel_launch(void* const* d_in, const int* in_sizes, int n_in,
                              void* d_out, int out_size) {
    const float* base   = nullptr;
    const float* deltas = nullptr;
    const int*   env    = nullptr;
    for (int i = 0; i < n_in; i++) {
        if      (in_sizes[i] == DD)        base   = (const float*)d_in[i];
        else if (in_sizes[i] == NENV * DD) deltas = (const float*)d_in[i];
        else if (in_sizes[i] == NB)        env    = (const int*)d_in[i];
        // z_s (131072 elems) unused by the reference outputs
    }

    k_zero<<<256, 256>>>();

    dim3 gb(DD / 4096, NENV);            // (64, 4), 256 thr, 4 f4/thread
    k_build<<<gb, 256>>>(base, deltas);
    k_scan<<<NENV, 1024>>>(0, env);
    k_hist2<<<gb, 256>>>();
    k_scan<<<NENV, 1024>>>(1, env);

    float* outA = (float*)d_out;         // tuple order: (A, A_logits, A_soft)
    float* outL = outA + (size_t)NB * DD;
    float* outS = outL + (size_t)NB * DD;
    dim3 go(DD / 1024, NENV);            // (256, 4), 1 f4/thread, loop rows
    k_bcast<<<go, 256>>>(outA, outL, outS);
}

// round 4
// speedup vs baseline: 1.5431x; 1.5431x over previous
#include <cuda_runtime.h>

#define DD     262144     // 512*512
#define NB     128        // batch
#define NENV   4
#define KSEL   26214      // floor(0.1 * 512 * 512)
#define NBIN   65536

// Scratch (allocation-free: __device__ globals)
__device__ float    g_M[NENV][DD];        // per-env logits (4 MB, L2-resident)
__device__ float    g_S[NENV][DD];        // per-env sigmoid(logits)
__device__ unsigned g_hist[NENV][NBIN];   // radix pass 1 (hi 16 bits)
__device__ unsigned g_hist2[NENV][NBIN];  // radix pass 2 (lo 16 bits)
__device__ unsigned g_binhi[NENV];
__device__ unsigned g_rank[NENV];
__device__ unsigned g_kth[NENV];          // exact key of k-th largest per env

// Monotone mapping: float total order -> unsigned total order
__device__ __forceinline__ unsigned fkey(float f) {
    unsigned u = __float_as_uint(f);
    return (u & 0x80000000u) ? ~u : (u | 0x80000000u);
}
__device__ __forceinline__ float sigm(float x) {
    return __fdividef(1.0f, 1.0f + __expf(-x));   // MUFU EX2 + fast RCP
}

__global__ void k_zero() {
    int stride = gridDim.x * blockDim.x;
    unsigned* h1 = &g_hist[0][0];
    for (int j = blockIdx.x * blockDim.x + threadIdx.x; j < NENV * NBIN; j += stride)
        h1[j] = 0u;
}

// Build per-env logits + sigmoid + hi-16 histogram. Flat grid (high occupancy).
__global__ void k_build(const float* __restrict__ base, const float* __restrict__ deltas) {
    int e = blockIdx.y;
    int i = (blockIdx.x * 256 + threadIdx.x) * 4;
    float4 b4 = *(const float4*)(base + i);
    float4 d4 = *(const float4*)(deltas + (size_t)e * DD + i);
    float4 m;
    m.x = b4.x + d4.x; m.y = b4.y + d4.y;
    m.z = b4.z + d4.z; m.w = b4.w + d4.w;
    *(float4*)(&g_M[e][i]) = m;
    float4 s;
    s.x = sigm(m.x); s.y = sigm(m.y); s.z = sigm(m.z); s.w = sigm(m.w);
    *(float4*)(&g_S[e][i]) = s;
    atomicAdd(&g_hist[e][fkey(m.x) >> 16], 1u);
    atomicAdd(&g_hist[e][fkey(m.y) >> 16], 1u);
    atomicAdd(&g_hist[e][fkey(m.z) >> 16], 1u);
    atomicAdd(&g_hist[e][fkey(m.w) >> 16], 1u);
}

// Rank-select over a 65536-bin histogram (descending), parallel suffix-scan.
// phase 0: g_hist -> (binhi, remaining rank); also zeroes g_hist2.
// phase 1: g_hist2 -> exact kth key.
__global__ void k_scan(int phase) {
    int e = blockIdx.x;
    int t = threadIdx.x;
    const unsigned* h = (phase == 0) ? &g_hist[e][0] : &g_hist2[e][0];
    __shared__ unsigned ss[1024];

    unsigned s = 0;
    #pragma unroll 4
    for (int j = 0; j < 64; j++) {
        s += h[t * 64 + j];
        if (phase == 0) g_hist2[e][t * 64 + j] = 0u;   // prep pass 2
    }
    ss[t] = s;
    __syncthreads();
    // inclusive suffix sum: ss[t] = sum_{j>=t} chunk[j]
    for (int off = 1; off < 1024; off <<= 1) {
        unsigned v = (t + off < 1024) ? ss[t + off] : 0u;
        __syncthreads();
        ss[t] += v;
        __syncthreads();
    }
    unsigned target = (phase == 0) ? (unsigned)KSEL : g_rank[e];
    unsigned above = (t < 1023) ? ss[t + 1] : 0u;
    if (ss[t] >= target && above < target) {
        unsigned cum = above;
        unsigned bin = (unsigned)(t * 64);
        for (int j = 63; j >= 0; j--) {
            unsigned v = h[t * 64 + j];
            if (cum + v >= target) { bin = (unsigned)(t * 64 + j); break; }
            cum += v;
        }
        if (phase == 0) {
            g_binhi[e] = bin;
            g_rank[e]  = target - cum;
        } else {
            g_kth[e] = (g_binhi[e] << 16) | bin;
        }
    }
}

// Lo-16 histogram restricted to the selected hi-bin. Flat grid.
__global__ void k_hist2() {
    int e = blockIdx.y;
    unsigned hi = g_binhi[e];
    int i = (blockIdx.x * 256 + threadIdx.x) * 4;
    float4 m = *(const float4*)(&g_M[e][i]);
    unsigned k0 = fkey(m.x), k1 = fkey(m.y), k2 = fkey(m.z), k3 = fkey(m.w);
    if ((k0 >> 16) == hi) atomicAdd(&g_hist2[e][k0 & 0xFFFFu], 1u);
    if ((k1 >> 16) == hi) atomicAdd(&g_hist2[e][k1 & 0xFFFFu], 1u);
    if ((k2 >> 16) == hi) atomicAdd(&g_hist2[e][k2 & 0xFFFFu], 1u);
    if ((k3 >> 16) == hi) atomicAdd(&g_hist2[e][k3 & 0xFFFFu], 1u);
}

// Flat streaming writer: per (row-chunk, batch) block; reads M,S from L2,
// emits 3 dense coalesced float4 streams with evict-first stores.
__global__ void k_out(const int* __restrict__ env_idx,
                      float* __restrict__ outA,
                      float* __restrict__ outL,
                      float* __restrict__ outS) {
    int b = blockIdx.y;
    int e = __ldg(&env_idx[b]);
    unsigned kth = g_kth[e];
    size_t i = ((size_t)blockIdx.x * 256 + threadIdx.x) * 4;
    float4 m = *(const float4*)(&g_M[e][i]);
    float4 s = *(const float4*)(&g_S[e][i]);
    float4 a;
    a.x = (fkey(m.x) >= kth) ? s.x : 0.0f;
    a.y = (fkey(m.y) >= kth) ? s.y : 0.0f;
    a.z = (fkey(m.z) >= kth) ? s.z : 0.0f;
    a.w = (fkey(m.w) >= kth) ? s.w : 0.0f;
    size_t off = (size_t)b * DD + i;
    __stcs((float4*)(outA + off), a);
    __stcs((float4*)(outL + off), m);
    __stcs((float4*)(outS + off), s);
}

extern "C" void kernel_launch(void* const* d_in, const int* in_sizes, int n_in,
                              void* d_out, int out_size) {
    const float* base   = nullptr;
    const float* deltas = nullptr;
    const int*   env    = nullptr;
    for (int i = 0; i < n_in; i++) {
        if      (in_sizes[i] == DD)        base   = (const float*)d_in[i];
        else if (in_sizes[i] == NENV * DD) deltas = (const float*)d_in[i];
        else if (in_sizes[i] == NB)        env    = (const int*)d_in[i];
        // z_s (131072 elems) unused by the reference outputs
    }

    k_zero<<<128, 256>>>();                 // zero g_hist only (g_hist2 zeroed in k_scan(0))

    dim3 gb(DD / 1024, NENV);               // (256, 4): 1 float4/thread
    k_build<<<gb, 256>>>(base, deltas);
    k_scan<<<NENV, 1024>>>(0);
    k_hist2<<<gb, 256>>>();
    k_scan<<<NENV, 1024>>>(1);

    float* outA = (float*)d_out;            // tuple order: (A, A_logits, A_soft)
    float* outL = outA + (size_t)NB * DD;
    float* outS = outL + (size_t)NB * DD;
    dim3 go(DD / 1024, NB);                 // (256, 128): 1 float4/thread
    k_out<<<go, 256>>>(env, outA, outL, outS);
}